// round 13
// baseline (speedup 1.0000x reference)
#include <cuda_runtime.h>
#include <cstdint>

#define MAXN 50000
#define MAXE 1600000
#define D 64

// ---- scratch (__device__ globals; no allocations allowed) ----
__device__ float g_agg[MAXN * D];    // segment-sum of h_mu[dst] over src (fp32)
__device__ float g_Sx[MAXN * 4];     // per-src scalar sums: Spos, Sneg, Sw, pad
__device__ float g_hmu[MAXN * D];    // relu(mu @ W3^T)
__device__ float g_v[3 * D];         // v1=W4a@relu(W1), v1n=W4a@relu(-W1), v2=W4b@relu(W2)

__device__ __forceinline__ float relu(float a) { return fmaxf(a, 0.f); }

__device__ __forceinline__ void red_add_v4(float* addr, float4 v) {
    asm volatile("red.global.add.v4.f32 [%0], {%1,%2,%3,%4};"
                 :: "l"(addr), "f"(v.x), "f"(v.y), "f"(v.z), "f"(v.w)
                 : "memory");
}

// 4-node x 4-output register-tile GEMM inner loop over smem.
// sM: [nodes][64 k], sW: [64 k][64 o] (float4 columns).
__device__ __forceinline__ void gemm_tile_4x4(const float* sM, const float* sW,
                                              int gq, int o4, float4 acc[4]) {
    const float4* m0 = (const float4*)(sM + (gq * 4 + 0) * 64);
    const float4* m1 = (const float4*)(sM + (gq * 4 + 1) * 64);
    const float4* m2 = (const float4*)(sM + (gq * 4 + 2) * 64);
    const float4* m3 = (const float4*)(sM + (gq * 4 + 3) * 64);
    const float4* w4 = (const float4*)sW;
#pragma unroll
    for (int k4 = 0; k4 < 16; k4++) {
        float4 q0 = m0[k4], q1 = m1[k4], q2 = m2[k4], q3 = m3[k4];
        const float* f0 = &q0.x;
        const float* f1 = &q1.x;
        const float* f2 = &q2.x;
        const float* f3 = &q3.x;
#pragma unroll
        for (int r = 0; r < 4; r++) {
            float4 w = w4[(k4 * 4 + r) * 16 + o4];
            float s0 = f0[r], s1 = f1[r], s2 = f2[r], s3 = f3[r];
            acc[0].x = fmaf(s0, w.x, acc[0].x); acc[0].y = fmaf(s0, w.y, acc[0].y);
            acc[0].z = fmaf(s0, w.z, acc[0].z); acc[0].w = fmaf(s0, w.w, acc[0].w);
            acc[1].x = fmaf(s1, w.x, acc[1].x); acc[1].y = fmaf(s1, w.y, acc[1].y);
            acc[1].z = fmaf(s1, w.z, acc[1].z); acc[1].w = fmaf(s1, w.w, acc[1].w);
            acc[2].x = fmaf(s2, w.x, acc[2].x); acc[2].y = fmaf(s2, w.y, acc[2].y);
            acc[2].z = fmaf(s2, w.z, acc[2].z); acc[2].w = fmaf(s2, w.w, acc[2].w);
            acc[3].x = fmaf(s3, w.x, acc[3].x); acc[3].y = fmaf(s3, w.y, acc[3].y);
            acc[3].z = fmaf(s3, w.z, acc[3].z); acc[3].w = fmaf(s3, w.w, acc[3].w);
        }
    }
}

// K1: h_mu = relu(mu @ W3^T). 128 nodes/block, 512 threads, 4x4 register tile.
//     Prologue zeroes g_agg/g_Sx; block 0: vprep.
__global__ __launch_bounds__(512) void k_hmu_zero(const float* __restrict__ mu,
                                                  const float* __restrict__ W3,
                                                  const float* __restrict__ W1,
                                                  const float* __restrict__ W2,
                                                  const float* __restrict__ W4, int N) {
    int t = threadIdx.x;
    float4 z4 = make_float4(0.f, 0.f, 0.f, 0.f);
    int gsz = gridDim.x * 512;
    for (int i = blockIdx.x * 512 + t; i < N * 16; i += gsz) {
        ((float4*)g_agg)[i] = z4;
        if (i < N) ((float4*)g_Sx)[i] = z4;
    }

    __shared__ float sW3t[64 * 64];    // [k][o]  16 KB
    __shared__ float smu[128 * 64];    // [n_local][k]  32 KB
    for (int i = t; i < 64 * 64; i += 512) {
        int o = i >> 6, k = i & 63;
        sW3t[k * 64 + o] = W3[i];
    }
    int base = blockIdx.x * 128;
    for (int i = t; i < 128 * 16; i += 512) {
        int nl = i >> 4, q = i & 15;
        int n = base + nl;
        float4 m = (n < N) ? ((const float4*)mu)[(size_t)n * 16 + q] : z4;
        ((float4*)smu)[nl * 16 + q] = m;
    }
    __syncthreads();

    int gq = t >> 4, o4 = t & 15;      // gq in 0..31 -> rows gq*4..gq*4+3
    float4 acc[4] = {z4, z4, z4, z4};
    gemm_tile_4x4(smu, sW3t, gq, o4, acc);
#pragma unroll
    for (int r = 0; r < 4; r++) {
        int n = base + gq * 4 + r;
        if (n < N) {
            float4 a = acc[r];
            float4 rr = make_float4(relu(a.x), relu(a.y), relu(a.z), relu(a.w));
            ((float4*)g_hmu)[(size_t)n * 16 + o4] = rr;
        }
    }

    if (blockIdx.x == 0 && t < 64) {
        int o = t;
        float a = 0.f, b = 0.f, c = 0.f;
#pragma unroll 8
        for (int k = 0; k < 64; k++) {
            float w4a = W4[o * 192 + k];
            float w4b = W4[o * 192 + 64 + k];
            float w1 = W1[k], w2 = W2[k];
            a = fmaf(w4a, relu(w1), a);
            b = fmaf(w4a, relu(-w1), b);
            c = fmaf(w4b, relu(w2), c);
        }
        g_v[o] = a;
        g_v[64 + o] = b;
        g_v[128 + o] = c;
    }
}

// K2: scatter edge kernel (R9 measured-best form). 16 threads/group, 8 edges
// per group (MLP=8 on the fp32 float4 gathers), indices loaded as int4, then
// 8 fire-and-forget red.global.add.v4. Lane 0 reduces the 3 scalars.
__global__ __launch_bounds__(256) void k_edge(const int* __restrict__ ei,
                                              const float* __restrict__ x,
                                              const float* __restrict__ ew, int E) {
    int gid = (blockIdx.x * 256 + threadIdx.x) >> 4;
    int j = threadIdx.x & 15;
    int e0 = gid * 8;
    if (e0 >= E) return;
    const float4* hmu4 = (const float4*)g_hmu;

    if (e0 + 8 <= E) {
        int4 sa = *(const int4*)(ei + e0);
        int4 sb = *(const int4*)(ei + e0 + 4);
        int4 da = *(const int4*)(ei + (size_t)E + e0);
        int4 db = *(const int4*)(ei + (size_t)E + e0 + 4);
        int srcs[8] = {sa.x, sa.y, sa.z, sa.w, sb.x, sb.y, sb.z, sb.w};
        int dsts[8] = {da.x, da.y, da.z, da.w, db.x, db.y, db.z, db.w};
        float4 v[8];
#pragma unroll
        for (int q = 0; q < 8; q++)
            v[q] = hmu4[(size_t)dsts[q] * 16 + j];
#pragma unroll
        for (int q = 0; q < 8; q++)
            red_add_v4(&g_agg[(size_t)srcs[q] * 64 + (size_t)j * 4], v[q]);
        if (j == 0) {
#pragma unroll
            for (int q = 0; q < 8; q++) {
                float xd = x[dsts[q]];
                red_add_v4(&g_Sx[(size_t)srcs[q] * 4],
                           make_float4(relu(xd), relu(-xd), ew[e0 + q], 0.f));
            }
        }
    } else {
        for (int e = e0; e < E; e++) {
            int src = ei[e];
            int dst = ei[(size_t)E + e];
            float4 v = hmu4[(size_t)dst * 16 + j];
            red_add_v4(&g_agg[(size_t)src * 64 + (size_t)j * 4], v);
            if (j == 0) {
                float xd = x[dst];
                red_add_v4(&g_Sx[(size_t)src * 4],
                           make_float4(relu(xd), relu(-xd), ew[e], 0.f));
            }
        }
    }
}

// K3: finalize. 128 nodes/block, 512 threads, 4x4 register tile.
__global__ __launch_bounds__(512) void k_final(const float* __restrict__ x,
                                               const float* __restrict__ W1,
                                               const float* __restrict__ W4,
                                               float* __restrict__ out, int N) {
    __shared__ float sW4t[64 * 64];    // [k][o] of W4 cols 128..191
    __shared__ float sAgg[128 * 64];   // [n_local][k]
    __shared__ float sv[192];
    __shared__ float sW1[64];
    int t = threadIdx.x;
    float4 z4 = make_float4(0.f, 0.f, 0.f, 0.f);
    for (int i = t; i < 64 * 64; i += 512) {
        int o = i >> 6, k = i & 63;
        sW4t[k * 64 + o] = W4[o * 192 + 128 + k];
    }
    if (t < 192) sv[t] = g_v[t];
    if (t < 64)  sW1[t] = W1[t];
    int base = blockIdx.x * 128;
    for (int i = t; i < 128 * 16; i += 512) {
        int nl = i >> 4, q = i & 15;
        int n = base + nl;
        float4 a = (n < N) ? ((const float4*)g_agg)[(size_t)n * 16 + q] : z4;
        ((float4*)sAgg)[nl * 16 + q] = a;
    }
    __syncthreads();

    int gq = t >> 4, o4 = t & 15;
    int o0 = o4 * 4;
    float4 acc[4] = {z4, z4, z4, z4};
    gemm_tile_4x4(sAgg, sW4t, gq, o4, acc);

    float4 v1  = make_float4(sv[o0], sv[o0 + 1], sv[o0 + 2], sv[o0 + 3]);
    float4 v1n = make_float4(sv[64 + o0], sv[64 + o0 + 1], sv[64 + o0 + 2], sv[64 + o0 + 3]);
    float4 v2  = make_float4(sv[128 + o0], sv[128 + o0 + 1], sv[128 + o0 + 2], sv[128 + o0 + 3]);
    float4 w1v = make_float4(sW1[o0], sW1[o0 + 1], sW1[o0 + 2], sW1[o0 + 3]);
#pragma unroll
    for (int r = 0; r < 4; r++) {
        int n = base + gq * 4 + r;
        if (n >= N) break;
        float4 sx = ((const float4*)g_Sx)[n];
        float4 z = acc[r];
        z.x += sx.x * v1.x + sx.y * v1n.x + sx.z * v2.x;
        z.y += sx.x * v1.y + sx.y * v1n.y + sx.z * v2.y;
        z.z += sx.x * v1.z + sx.y * v1n.z + sx.z * v2.z;
        z.w += sx.x * v1.w + sx.y * v1n.w + sx.z * v2.w;
        float xn = x[n];
        float4 hm = ((const float4*)g_hmu)[(size_t)n * 16 + o4];
        float4 rr;
        rr.x = relu(relu(xn * w1v.x) + hm.x + relu(z.x));
        rr.y = relu(relu(xn * w1v.y) + hm.y + relu(z.y));
        rr.z = relu(relu(xn * w1v.z) + hm.z + relu(z.z));
        rr.w = relu(relu(xn * w1v.w) + hm.w + relu(z.w));
        ((float4*)out)[(size_t)n * 16 + o4] = rr;
    }
}

extern "C" void kernel_launch(void* const* d_in, const int* in_sizes, int n_in,
                              void* d_out, int out_size) {
    const float* mu  = (const float*)d_in[0];
    const float* x   = (const float*)d_in[1];
    const int*   ei  = (const int*)d_in[2];     // int32 (JAX x64 disabled)
    const float* ew  = (const float*)d_in[3];
    const float* W1  = (const float*)d_in[4];
    const float* W2  = (const float*)d_in[5];
    const float* W3  = (const float*)d_in[6];
    const float* W4  = (const float*)d_in[7];
    float* out = (float*)d_out;

    int N = in_sizes[1];   // x: [N,1]
    int E = in_sizes[3];   // edge_w: [E]

    k_hmu_zero<<<(N + 127) / 128, 512>>>(mu, W3, W1, W2, W4, N);

    int ngroups = (E + 7) / 8;                       // 8 edges per 16-thread group
    int blocks = (ngroups * 16 + 255) / 256;
    k_edge<<<blocks, 256>>>(ei, x, ew, E);

    k_final<<<(N + 127) / 128, 512>>>(x, W1, W4, out, N);
}

// round 14
// speedup vs baseline: 1.2834x; 1.2834x over previous
#include <cuda_runtime.h>
#include <cstdint>

#define MAXN 50000
#define MAXE 1600000
#define D 64

// ---- scratch (__device__ globals; no allocations allowed) ----
__device__ float g_agg[MAXN * D];    // segment-sum of h_mu[dst] over src (fp32)
__device__ float g_Sx[MAXN * 4];     // per-src scalar sums: Spos, Sneg, Sw, pad
__device__ float g_hmu[MAXN * D];    // relu(mu @ W3^T)
__device__ float g_v[3 * D];         // v1=W4a@relu(W1), v1n=W4a@relu(-W1), v2=W4b@relu(W2)

__device__ __forceinline__ float relu(float a) { return fmaxf(a, 0.f); }

__device__ __forceinline__ void red_add_v4(float* addr, float4 v) {
    asm volatile("red.global.add.v4.f32 [%0], {%1,%2,%3,%4};"
                 :: "l"(addr), "f"(v.x), "f"(v.y), "f"(v.z), "f"(v.w)
                 : "memory");
}

// 4-node x 4-output register-tile GEMM inner loop over smem.
// sM: [64 nodes][64 k], sW: [64 k][64 o] (float4 columns).
__device__ __forceinline__ void gemm_tile_4x4(const float* sM, const float* sW,
                                              int gq, int o4, float4 acc[4]) {
    const float4* m0 = (const float4*)(sM + (gq * 4 + 0) * 64);
    const float4* m1 = (const float4*)(sM + (gq * 4 + 1) * 64);
    const float4* m2 = (const float4*)(sM + (gq * 4 + 2) * 64);
    const float4* m3 = (const float4*)(sM + (gq * 4 + 3) * 64);
    const float4* w4 = (const float4*)sW;
#pragma unroll
    for (int k4 = 0; k4 < 16; k4++) {
        float4 q0 = m0[k4], q1 = m1[k4], q2 = m2[k4], q3 = m3[k4];
        const float* f0 = &q0.x;
        const float* f1 = &q1.x;
        const float* f2 = &q2.x;
        const float* f3 = &q3.x;
#pragma unroll
        for (int r = 0; r < 4; r++) {
            float4 w = w4[(k4 * 4 + r) * 16 + o4];
            float s0 = f0[r], s1 = f1[r], s2 = f2[r], s3 = f3[r];
            acc[0].x = fmaf(s0, w.x, acc[0].x); acc[0].y = fmaf(s0, w.y, acc[0].y);
            acc[0].z = fmaf(s0, w.z, acc[0].z); acc[0].w = fmaf(s0, w.w, acc[0].w);
            acc[1].x = fmaf(s1, w.x, acc[1].x); acc[1].y = fmaf(s1, w.y, acc[1].y);
            acc[1].z = fmaf(s1, w.z, acc[1].z); acc[1].w = fmaf(s1, w.w, acc[1].w);
            acc[2].x = fmaf(s2, w.x, acc[2].x); acc[2].y = fmaf(s2, w.y, acc[2].y);
            acc[2].z = fmaf(s2, w.z, acc[2].z); acc[2].w = fmaf(s2, w.w, acc[2].w);
            acc[3].x = fmaf(s3, w.x, acc[3].x); acc[3].y = fmaf(s3, w.y, acc[3].y);
            acc[3].z = fmaf(s3, w.z, acc[3].z); acc[3].w = fmaf(s3, w.w, acc[3].w);
        }
    }
}

// K1: h_mu = relu(mu @ W3^T). 64 nodes/block, 256 threads, 4x4 register tile
//     (measured-best shape). Prologue zeroes g_agg/g_Sx; block 0: vprep.
__global__ __launch_bounds__(256) void k_hmu_zero(const float* __restrict__ mu,
                                                  const float* __restrict__ W3,
                                                  const float* __restrict__ W1,
                                                  const float* __restrict__ W2,
                                                  const float* __restrict__ W4, int N) {
    int t = threadIdx.x;
    float4 z4 = make_float4(0.f, 0.f, 0.f, 0.f);
    int gsz = gridDim.x * 256;
    for (int i = blockIdx.x * 256 + t; i < N * 16; i += gsz) {
        ((float4*)g_agg)[i] = z4;
        if (i < N) ((float4*)g_Sx)[i] = z4;
    }

    __shared__ float sW3t[64 * 64];   // [k][o]
    __shared__ float smu[64 * 64];    // [n_local][k]
    for (int i = t; i < 64 * 64; i += 256) {
        int o = i >> 6, k = i & 63;
        sW3t[k * 64 + o] = W3[i];
    }
    int base = blockIdx.x * 64;
    for (int i = t; i < 64 * 16; i += 256) {
        int nl = i >> 4, q = i & 15;
        int n = base + nl;
        float4 m = (n < N) ? ((const float4*)mu)[(size_t)n * 16 + q] : z4;
        ((float4*)smu)[nl * 16 + q] = m;
    }
    __syncthreads();

    int gq = t >> 4, o4 = t & 15;
    float4 acc[4] = {z4, z4, z4, z4};
    gemm_tile_4x4(smu, sW3t, gq, o4, acc);
#pragma unroll
    for (int r = 0; r < 4; r++) {
        int n = base + gq * 4 + r;
        if (n < N) {
            float4 a = acc[r];
            float4 rr = make_float4(relu(a.x), relu(a.y), relu(a.z), relu(a.w));
            ((float4*)g_hmu)[(size_t)n * 16 + o4] = rr;
        }
    }

    if (blockIdx.x == 0 && t < 64) {
        int o = t;
        float a = 0.f, b = 0.f, c = 0.f;
#pragma unroll 8
        for (int k = 0; k < 64; k++) {
            float w4a = W4[o * 192 + k];
            float w4b = W4[o * 192 + 64 + k];
            float w1 = W1[k], w2 = W2[k];
            a = fmaf(w4a, relu(w1), a);
            b = fmaf(w4a, relu(-w1), b);
            c = fmaf(w4b, relu(w2), c);
        }
        g_v[o] = a;
        g_v[64 + o] = b;
        g_v[128 + o] = c;
    }
}

// K2: scatter edge kernel. 16 threads/group, 8 edges/group (MLP=8 fp32 float4
// gathers), indices as int4, fire-and-forget red.global.add.v4 into agg[src].
// Scalar triples issued in PARALLEL by lanes 0..7 (one edge each).
__global__ __launch_bounds__(256) void k_edge(const int* __restrict__ ei,
                                              const float* __restrict__ x,
                                              const float* __restrict__ ew, int E) {
    int gid = (blockIdx.x * 256 + threadIdx.x) >> 4;
    int j = threadIdx.x & 15;
    int e0 = gid * 8;
    if (e0 >= E) return;
    const float4* hmu4 = (const float4*)g_hmu;

    if (e0 + 8 <= E) {
        int4 sa = *(const int4*)(ei + e0);
        int4 sb = *(const int4*)(ei + e0 + 4);
        int4 da = *(const int4*)(ei + (size_t)E + e0);
        int4 db = *(const int4*)(ei + (size_t)E + e0 + 4);
        int srcs[8] = {sa.x, sa.y, sa.z, sa.w, sb.x, sb.y, sb.z, sb.w};
        int dsts[8] = {da.x, da.y, da.z, da.w, db.x, db.y, db.z, db.w};
        float4 v[8];
#pragma unroll
        for (int q = 0; q < 8; q++)
            v[q] = hmu4[(size_t)dsts[q] * 16 + j];
#pragma unroll
        for (int q = 0; q < 8; q++)
            red_add_v4(&g_agg[(size_t)srcs[q] * 64 + (size_t)j * 4], v[q]);
        if (j < 8) {      // lanes 0..7: one edge's scalar triple each
            int q = j;
            float xd = x[dsts[q]];
            red_add_v4(&g_Sx[(size_t)srcs[q] * 4],
                       make_float4(relu(xd), relu(-xd), ew[e0 + q], 0.f));
        }
    } else {
        for (int e = e0; e < E; e++) {
            int src = ei[e];
            int dst = ei[(size_t)E + e];
            float4 v = hmu4[(size_t)dst * 16 + j];
            red_add_v4(&g_agg[(size_t)src * 64 + (size_t)j * 4], v);
            if (j == 0) {
                float xd = x[dst];
                red_add_v4(&g_Sx[(size_t)src * 4],
                           make_float4(relu(xd), relu(-xd), ew[e], 0.f));
            }
        }
    }
}

// K3: finalize. 64 nodes/block, 256 threads, 4x4 register tile (measured-best).
__global__ __launch_bounds__(256) void k_final(const float* __restrict__ x,
                                               const float* __restrict__ W1,
                                               const float* __restrict__ W4,
                                               float* __restrict__ out, int N) {
    __shared__ float sW4t[64 * 64];   // [k][o] of W4 cols 128..191
    __shared__ float sAgg[64 * 64];   // [n_local][k]
    __shared__ float sv[192];
    __shared__ float sW1[64];
    int t = threadIdx.x;
    float4 z4 = make_float4(0.f, 0.f, 0.f, 0.f);
    for (int i = t; i < 64 * 64; i += 256) {
        int o = i >> 6, k = i & 63;
        sW4t[k * 64 + o] = W4[o * 192 + 128 + k];
    }
    if (t < 192) sv[t] = g_v[t];
    if (t < 64)  sW1[t] = W1[t];
    int base = blockIdx.x * 64;
    for (int i = t; i < 64 * 16; i += 256) {
        int nl = i >> 4, q = i & 15;
        int n = base + nl;
        float4 a = (n < N) ? ((const float4*)g_agg)[(size_t)n * 16 + q] : z4;
        ((float4*)sAgg)[nl * 16 + q] = a;
    }
    __syncthreads();

    int gq = t >> 4, o4 = t & 15;
    int o0 = o4 * 4;
    float4 acc[4] = {z4, z4, z4, z4};
    gemm_tile_4x4(sAgg, sW4t, gq, o4, acc);

    float4 v1  = make_float4(sv[o0], sv[o0 + 1], sv[o0 + 2], sv[o0 + 3]);
    float4 v1n = make_float4(sv[64 + o0], sv[64 + o0 + 1], sv[64 + o0 + 2], sv[64 + o0 + 3]);
    float4 v2  = make_float4(sv[128 + o0], sv[128 + o0 + 1], sv[128 + o0 + 2], sv[128 + o0 + 3]);
    float4 w1v = make_float4(sW1[o0], sW1[o0 + 1], sW1[o0 + 2], sW1[o0 + 3]);
#pragma unroll
    for (int r = 0; r < 4; r++) {
        int n = base + gq * 4 + r;
        if (n >= N) break;
        float4 sx = ((const float4*)g_Sx)[n];
        float4 z = acc[r];
        z.x += sx.x * v1.x + sx.y * v1n.x + sx.z * v2.x;
        z.y += sx.x * v1.y + sx.y * v1n.y + sx.z * v2.y;
        z.z += sx.x * v1.z + sx.y * v1n.z + sx.z * v2.z;
        z.w += sx.x * v1.w + sx.y * v1n.w + sx.z * v2.w;
        float xn = x[n];
        float4 hm = ((const float4*)g_hmu)[(size_t)n * 16 + o4];
        float4 rr;
        rr.x = relu(relu(xn * w1v.x) + hm.x + relu(z.x));
        rr.y = relu(relu(xn * w1v.y) + hm.y + relu(z.y));
        rr.z = relu(relu(xn * w1v.z) + hm.z + relu(z.z));
        rr.w = relu(relu(xn * w1v.w) + hm.w + relu(z.w));
        ((float4*)out)[(size_t)n * 16 + o4] = rr;
    }
}

extern "C" void kernel_launch(void* const* d_in, const int* in_sizes, int n_in,
                              void* d_out, int out_size) {
    const float* mu  = (const float*)d_in[0];
    const float* x   = (const float*)d_in[1];
    const int*   ei  = (const int*)d_in[2];     // int32 (JAX x64 disabled)
    const float* ew  = (const float*)d_in[3];
    const float* W1  = (const float*)d_in[4];
    const float* W2  = (const float*)d_in[5];
    const float* W3  = (const float*)d_in[6];
    const float* W4  = (const float*)d_in[7];
    float* out = (float*)d_out;

    int N = in_sizes[1];   // x: [N,1]
    int E = in_sizes[3];   // edge_w: [E]

    k_hmu_zero<<<(N + 63) / 64, 256>>>(mu, W3, W1, W2, W4, N);

    int ngroups = (E + 7) / 8;                       // 8 edges per 16-thread group
    int blocks = (ngroups * 16 + 255) / 256;
    k_edge<<<blocks, 256>>>(ei, x, ew, E);

    k_final<<<(N + 63) / 64, 256>>>(x, W1, W4, out, N);
}

// round 15
// speedup vs baseline: 1.5045x; 1.1723x over previous
#include <cuda_runtime.h>
#include <cstdint>

#define MAXN 50000
#define MAXE 1600000
#define D 64

// ---- scratch (__device__ globals; no allocations allowed) ----
__device__ float g_agg[MAXN * D];    // segment-sum of h_mu[dst] over src (fp32)
__device__ float g_Sx[MAXN * 4];     // per-src scalar sums: Spos, Sneg, Sw, pad
__device__ float g_hmu[MAXN * D];    // relu(mu @ W3^T)
__device__ float g_v[3 * D];         // v1=W4a@relu(W1), v1n=W4a@relu(-W1), v2=W4b@relu(W2)

__device__ __forceinline__ float relu(float a) { return fmaxf(a, 0.f); }

__device__ __forceinline__ void red_add_v4(float* addr, float4 v) {
    asm volatile("red.global.add.v4.f32 [%0], {%1,%2,%3,%4};"
                 :: "l"(addr), "f"(v.x), "f"(v.y), "f"(v.z), "f"(v.w)
                 : "memory");
}

// 4-node x 4-output register-tile GEMM inner loop over smem.
// sM: [64 nodes][64 k], sW: [64 k][64 o] (float4 columns).
__device__ __forceinline__ void gemm_tile_4x4(const float* sM, const float* sW,
                                              int gq, int o4, float4 acc[4]) {
    const float4* m0 = (const float4*)(sM + (gq * 4 + 0) * 64);
    const float4* m1 = (const float4*)(sM + (gq * 4 + 1) * 64);
    const float4* m2 = (const float4*)(sM + (gq * 4 + 2) * 64);
    const float4* m3 = (const float4*)(sM + (gq * 4 + 3) * 64);
    const float4* w4 = (const float4*)sW;
#pragma unroll
    for (int k4 = 0; k4 < 16; k4++) {
        float4 q0 = m0[k4], q1 = m1[k4], q2 = m2[k4], q3 = m3[k4];
        const float* f0 = &q0.x;
        const float* f1 = &q1.x;
        const float* f2 = &q2.x;
        const float* f3 = &q3.x;
#pragma unroll
        for (int r = 0; r < 4; r++) {
            float4 w = w4[(k4 * 4 + r) * 16 + o4];
            float s0 = f0[r], s1 = f1[r], s2 = f2[r], s3 = f3[r];
            acc[0].x = fmaf(s0, w.x, acc[0].x); acc[0].y = fmaf(s0, w.y, acc[0].y);
            acc[0].z = fmaf(s0, w.z, acc[0].z); acc[0].w = fmaf(s0, w.w, acc[0].w);
            acc[1].x = fmaf(s1, w.x, acc[1].x); acc[1].y = fmaf(s1, w.y, acc[1].y);
            acc[1].z = fmaf(s1, w.z, acc[1].z); acc[1].w = fmaf(s1, w.w, acc[1].w);
            acc[2].x = fmaf(s2, w.x, acc[2].x); acc[2].y = fmaf(s2, w.y, acc[2].y);
            acc[2].z = fmaf(s2, w.z, acc[2].z); acc[2].w = fmaf(s2, w.w, acc[2].w);
            acc[3].x = fmaf(s3, w.x, acc[3].x); acc[3].y = fmaf(s3, w.y, acc[3].y);
            acc[3].z = fmaf(s3, w.z, acc[3].z); acc[3].w = fmaf(s3, w.w, acc[3].w);
        }
    }
}

// K1: h_mu = relu(mu @ W3^T). 64 nodes/block, 256 threads, 4x4 register tile
//     (measured-best shape). Prologue zeroes g_agg/g_Sx; block 0: vprep.
__global__ __launch_bounds__(256) void k_hmu_zero(const float* __restrict__ mu,
                                                  const float* __restrict__ W3,
                                                  const float* __restrict__ W1,
                                                  const float* __restrict__ W2,
                                                  const float* __restrict__ W4, int N) {
    int t = threadIdx.x;
    float4 z4 = make_float4(0.f, 0.f, 0.f, 0.f);
    int gsz = gridDim.x * 256;
    for (int i = blockIdx.x * 256 + t; i < N * 16; i += gsz) {
        ((float4*)g_agg)[i] = z4;
        if (i < N) ((float4*)g_Sx)[i] = z4;
    }

    __shared__ float sW3t[64 * 64];   // [k][o]
    __shared__ float smu[64 * 64];    // [n_local][k]
    for (int i = t; i < 64 * 64; i += 256) {
        int o = i >> 6, k = i & 63;
        sW3t[k * 64 + o] = W3[i];
    }
    int base = blockIdx.x * 64;
    for (int i = t; i < 64 * 16; i += 256) {
        int nl = i >> 4, q = i & 15;
        int n = base + nl;
        float4 m = (n < N) ? ((const float4*)mu)[(size_t)n * 16 + q] : z4;
        ((float4*)smu)[nl * 16 + q] = m;
    }
    __syncthreads();

    int gq = t >> 4, o4 = t & 15;
    float4 acc[4] = {z4, z4, z4, z4};
    gemm_tile_4x4(smu, sW3t, gq, o4, acc);
#pragma unroll
    for (int r = 0; r < 4; r++) {
        int n = base + gq * 4 + r;
        if (n < N) {
            float4 a = acc[r];
            float4 rr = make_float4(relu(a.x), relu(a.y), relu(a.z), relu(a.w));
            ((float4*)g_hmu)[(size_t)n * 16 + o4] = rr;
        }
    }

    if (blockIdx.x == 0 && t < 64) {
        int o = t;
        float a = 0.f, b = 0.f, c = 0.f;
#pragma unroll 8
        for (int k = 0; k < 64; k++) {
            float w4a = W4[o * 192 + k];
            float w4b = W4[o * 192 + 64 + k];
            float w1 = W1[k], w2 = W2[k];
            a = fmaf(w4a, relu(w1), a);
            b = fmaf(w4a, relu(-w1), b);
            c = fmaf(w4b, relu(w2), c);
        }
        g_v[o] = a;
        g_v[64 + o] = b;
        g_v[128 + o] = c;
    }
}

// K2: scatter edge kernel (measured-best R9 form). 16 threads/group, 8 edges
// per group (MLP=8 on the fp32 float4 gathers), indices loaded as int4, then
// 8 fire-and-forget red.global.add.v4. Lane 0 serially issues the 3-scalar
// triples (predicated-off on lanes 1..15; overlaps with in-flight v4 REDs —
// the lane-distributed variant measured 24us slower).
__global__ __launch_bounds__(256) void k_edge(const int* __restrict__ ei,
                                              const float* __restrict__ x,
                                              const float* __restrict__ ew, int E) {
    int gid = (blockIdx.x * 256 + threadIdx.x) >> 4;
    int j = threadIdx.x & 15;
    int e0 = gid * 8;
    if (e0 >= E) return;
    const float4* hmu4 = (const float4*)g_hmu;

    if (e0 + 8 <= E) {
        int4 sa = *(const int4*)(ei + e0);
        int4 sb = *(const int4*)(ei + e0 + 4);
        int4 da = *(const int4*)(ei + (size_t)E + e0);
        int4 db = *(const int4*)(ei + (size_t)E + e0 + 4);
        int srcs[8] = {sa.x, sa.y, sa.z, sa.w, sb.x, sb.y, sb.z, sb.w};
        int dsts[8] = {da.x, da.y, da.z, da.w, db.x, db.y, db.z, db.w};
        float4 v[8];
#pragma unroll
        for (int q = 0; q < 8; q++)
            v[q] = hmu4[(size_t)dsts[q] * 16 + j];
#pragma unroll
        for (int q = 0; q < 8; q++)
            red_add_v4(&g_agg[(size_t)srcs[q] * 64 + (size_t)j * 4], v[q]);
        if (j == 0) {
#pragma unroll
            for (int q = 0; q < 8; q++) {
                float xd = x[dsts[q]];
                red_add_v4(&g_Sx[(size_t)srcs[q] * 4],
                           make_float4(relu(xd), relu(-xd), ew[e0 + q], 0.f));
            }
        }
    } else {
        for (int e = e0; e < E; e++) {
            int src = ei[e];
            int dst = ei[(size_t)E + e];
            float4 v = hmu4[(size_t)dst * 16 + j];
            red_add_v4(&g_agg[(size_t)src * 64 + (size_t)j * 4], v);
            if (j == 0) {
                float xd = x[dst];
                red_add_v4(&g_Sx[(size_t)src * 4],
                           make_float4(relu(xd), relu(-xd), ew[e], 0.f));
            }
        }
    }
}

// K3: finalize. 64 nodes/block, 256 threads, 4x4 register tile (measured-best).
__global__ __launch_bounds__(256) void k_final(const float* __restrict__ x,
                                               const float* __restrict__ W1,
                                               const float* __restrict__ W4,
                                               float* __restrict__ out, int N) {
    __shared__ float sW4t[64 * 64];   // [k][o] of W4 cols 128..191
    __shared__ float sAgg[64 * 64];   // [n_local][k]
    __shared__ float sv[192];
    __shared__ float sW1[64];
    int t = threadIdx.x;
    float4 z4 = make_float4(0.f, 0.f, 0.f, 0.f);
    for (int i = t; i < 64 * 64; i += 256) {
        int o = i >> 6, k = i & 63;
        sW4t[k * 64 + o] = W4[o * 192 + 128 + k];
    }
    if (t < 192) sv[t] = g_v[t];
    if (t < 64)  sW1[t] = W1[t];
    int base = blockIdx.x * 64;
    for (int i = t; i < 64 * 16; i += 256) {
        int nl = i >> 4, q = i & 15;
        int n = base + nl;
        float4 a = (n < N) ? ((const float4*)g_agg)[(size_t)n * 16 + q] : z4;
        ((float4*)sAgg)[nl * 16 + q] = a;
    }
    __syncthreads();

    int gq = t >> 4, o4 = t & 15;
    int o0 = o4 * 4;
    float4 acc[4] = {z4, z4, z4, z4};
    gemm_tile_4x4(sAgg, sW4t, gq, o4, acc);

    float4 v1  = make_float4(sv[o0], sv[o0 + 1], sv[o0 + 2], sv[o0 + 3]);
    float4 v1n = make_float4(sv[64 + o0], sv[64 + o0 + 1], sv[64 + o0 + 2], sv[64 + o0 + 3]);
    float4 v2  = make_float4(sv[128 + o0], sv[128 + o0 + 1], sv[128 + o0 + 2], sv[128 + o0 + 3]);
    float4 w1v = make_float4(sW1[o0], sW1[o0 + 1], sW1[o0 + 2], sW1[o0 + 3]);
#pragma unroll
    for (int r = 0; r < 4; r++) {
        int n = base + gq * 4 + r;
        if (n >= N) break;
        float4 sx = ((const float4*)g_Sx)[n];
        float4 z = acc[r];
        z.x += sx.x * v1.x + sx.y * v1n.x + sx.z * v2.x;
        z.y += sx.x * v1.y + sx.y * v1n.y + sx.z * v2.y;
        z.z += sx.x * v1.z + sx.y * v1n.z + sx.z * v2.z;
        z.w += sx.x * v1.w + sx.y * v1n.w + sx.z * v2.w;
        float xn = x[n];
        float4 hm = ((const float4*)g_hmu)[(size_t)n * 16 + o4];
        float4 rr;
        rr.x = relu(relu(xn * w1v.x) + hm.x + relu(z.x));
        rr.y = relu(relu(xn * w1v.y) + hm.y + relu(z.y));
        rr.z = relu(relu(xn * w1v.z) + hm.z + relu(z.z));
        rr.w = relu(relu(xn * w1v.w) + hm.w + relu(z.w));
        ((float4*)out)[(size_t)n * 16 + o4] = rr;
    }
}

extern "C" void kernel_launch(void* const* d_in, const int* in_sizes, int n_in,
                              void* d_out, int out_size) {
    const float* mu  = (const float*)d_in[0];
    const float* x   = (const float*)d_in[1];
    const int*   ei  = (const int*)d_in[2];     // int32 (JAX x64 disabled)
    const float* ew  = (const float*)d_in[3];
    const float* W1  = (const float*)d_in[4];
    const float* W2  = (const float*)d_in[5];
    const float* W3  = (const float*)d_in[6];
    const float* W4  = (const float*)d_in[7];
    float* out = (float*)d_out;

    int N = in_sizes[1];   // x: [N,1]
    int E = in_sizes[3];   // edge_w: [E]

    k_hmu_zero<<<(N + 63) / 64, 256>>>(mu, W3, W1, W2, W4, N);

    int ngroups = (E + 7) / 8;                       // 8 edges per 16-thread group
    int blocks = (ngroups * 16 + 255) / 256;
    k_edge<<<blocks, 256>>>(ei, x, ew, E);

    k_final<<<(N + 63) / 64, 256>>>(x, W1, W4, out, N);
}